// round 15
// baseline (speedup 1.0000x reference)
#include <cuda_runtime.h>
#include <cuda_bf16.h>
#include <cstdint>

#define NN 500000
#define ND 128
#define NH 64
#define NG 16384
#define TB 256                     // 8 warps per CTA
#define GRID 608                   // 4 CTAs/SM x 152 SMs (full residency set)
#define NTILE (NN / 16)            // 31250 warp-tiles of 16 nodes (exact)
#define NWARPS (GRID * 8)          // 4864 initial tiles via warp id

#define WPITCH 136                 // bf16 per W row (272B = 17*16B: LDSM conflict-free)

__device__ int g_batch_is64;
__device__ unsigned g_ctr;

// Zero graph-energy slots; seed the work-stealing counter; detect batch dtype
// (word NN-1 is the zero int64 high half iff batch stored as int64).
__global__ void init_kernel(float* __restrict__ out, const int* __restrict__ bw) {
    int i = blockIdx.x * blockDim.x + threadIdx.x;
    if (i < NG) out[NN + i] = 0.0f;
    if (i == 0) { g_batch_is64 = (bw[NN - 1] == 0) ? 1 : 0; g_ctr = NWARPS; }
}

__device__ __forceinline__ uint32_t smem_u32(const void* p) {
    uint32_t a;
    asm("{ .reg .u64 t; cvta.to.shared.u64 t, %1; cvt.u32.u64 %0, t; }" : "=r"(a) : "l"(p));
    return a;
}

__device__ __forceinline__ uint32_t pack2(float x, float y) {   // lo half = x
    __nv_bfloat162 h = __floats2bfloat162_rn(x, y);
    return *(uint32_t*)&h;
}

__device__ __forceinline__ void ldsm4(uint32_t* r, uint32_t addr) {
    asm volatile("ldmatrix.sync.aligned.m8n8.x4.shared.b16 {%0,%1,%2,%3}, [%4];"
                 : "=r"(r[0]), "=r"(r[1]), "=r"(r[2]), "=r"(r[3]) : "r"(addr));
}

__device__ __forceinline__ void mma16816(float* d, const uint32_t* a,
                                         uint32_t b0, uint32_t b1) {
    asm volatile(
        "mma.sync.aligned.m16n8k16.row.col.f32.bf16.bf16.f32 "
        "{%0,%1,%2,%3}, {%4,%5,%6,%7}, {%8,%9}, {%0,%1,%2,%3};"
        : "+f"(d[0]), "+f"(d[1]), "+f"(d[2]), "+f"(d[3])
        : "r"(a[0]), "r"(a[1]), "r"(a[2]), "r"(a[3]), "r"(b0), "r"(b1));
}

__device__ __forceinline__ float tanhf_approx(float x) {
    float y;
    asm("tanh.approx.f32 %0, %1;" : "=f"(y) : "f"(x));
    return y;
}

__device__ __forceinline__ void prefetch_l2(const void* p) {
    asm volatile("prefetch.global.L2 [%0];" :: "l"(p));
}

// K-permutation (per 16-col chunk): thread tg supplies logical cols
// {2tg,2tg+1,2tg+8,2tg+9} -> physical {4tg..4tg+3}, so A fragments are one
// float4 per row. W1 staged with the same permutation:
// physical pair p (0..7 in-group) -> logical slot (p&1)*4 + (p>>1).

__global__ __launch_bounds__(TB, 4)
void mlp_kernel(const float* __restrict__ X,
                const float* __restrict__ aein,
                const void*  __restrict__ batch,
                const float* __restrict__ W1,
                const float* __restrict__ b1,
                const float* __restrict__ W2,
                const float* __restrict__ b2,
                float* __restrict__ out)
{
    __shared__ __nv_bfloat16 Ws[NH * WPITCH];   // 17408 B (k-permuted)
    __shared__ float b1s[NH], w2h[NH];          // w2h = W2 * 0.5

    const int tid  = threadIdx.x;
    const int lane = tid & 31;
    const int wid  = tid >> 5;
    const int g  = lane >> 2;
    const int tg = lane & 3;

    // ---- Stage W1 once per CTA (bf16 RN, k-permuted) ----
    #pragma unroll
    for (int q = 0; q < 16; q++) {
        int idx = tid + q * TB;          // 4096 pairs
        int row = idx >> 6;
        int p   = idx & 63;
        int grp = p >> 3;
        int pp  = p & 7;
        int lq  = ((pp & 1) << 2) | (pp >> 1);
        float2 v = *(const float2*)(W1 + (size_t)row * ND + p * 2);
        *(uint32_t*)(Ws + row * WPITCH + grp * 16 + lq * 2) = pack2(v.x, v.y);
    }
    if (tid < NH) { b1s[tid] = b1[tid]; w2h[tid] = 0.5f * W2[tid]; }
    __syncthreads();

    const uint32_t smW = smem_u32(Ws);
    const int bline = (lane & 7) + ((lane >> 4) << 3);
    const int bkoff = (lane & 8) ? 8 : 0;
    const float bb = __ldg(b2);

    // prefetch lane mapping: 16 rows x 4 lines = 64 lines; 32 lanes x 2
    const int pf_row  = lane & 15;
    const int pf_line = (lane >> 4) * 2;

    // ---- Per-warp work-stealing over 16-node tiles ----
    unsigned my = blockIdx.x * 8 + wid;          // first tile = global warp id
    while (my < NTILE) {
        // steal the next tile early; prefetch it into L2 under this tile's work
        unsigned nxt;
        if (lane == 0) nxt = atomicAdd(&g_ctr, 1u);
        nxt = __shfl_sync(0xFFFFFFFFu, nxt, 0);
        if (nxt < NTILE) {
            const char* base = (const char*)(X + ((long)nxt * 16 + pf_row) * (long)ND);
            prefetch_l2(base + pf_line * 128);
            prefetch_l2(base + (pf_line + 1) * 128);
            if (lane == 0) prefetch_l2(aein + nxt * 16);
        }

        // ---- A fragments from global X (exact tiles: no OOB) ----
        long rg  = (long)my * 16 + g;
        long rg8 = rg + 8;
        const float* pA0 = X + rg  * (long)ND + tg * 4;
        const float* pA1 = X + rg8 * (long)ND + tg * 4;

        uint32_t af[8][4];
        #pragma unroll
        for (int k = 0; k < 8; k++) {
            float4 f0 = *(const float4*)(pA0 + k * 16);
            float4 f1 = *(const float4*)(pA1 + k * 16);
            af[k][0] = pack2(f0.x, f0.y);
            af[k][2] = pack2(f0.z, f0.w);
            af[k][1] = pack2(f1.x, f1.y);
            af[k][3] = pack2(f1.z, f1.w);
        }

        // ---- GEMM + fused epilogue over 4 col-tile pairs ----
        float ps0 = 0.0f, ps1 = 0.0f;
        #pragma unroll
        for (int jp = 0; jp < 4; jp++) {
            float acc0[4] = {0.f, 0.f, 0.f, 0.f};
            float acc1[4] = {0.f, 0.f, 0.f, 0.f};
            #pragma unroll
            for (int k = 0; k < 8; k++) {
                uint32_t bf[4];
                ldsm4(bf, smW + (uint32_t)(((jp * 16 + bline) * WPITCH + k * 16 + bkoff) * 2));
                mma16816(acc0, af[k], bf[0], bf[1]);
                mma16816(acc1, af[k], bf[2], bf[3]);
            }
            // silu(h)*w2 = (h*w2/2) * (1 + tanh(h/2)); 1 MUFU per h
            #pragma unroll
            for (int t = 0; t < 2; t++) {
                const float* ac = t ? acc1 : acc0;
                int c0 = (jp * 2 + t) * 8 + tg * 2;
                float2 bv = *(const float2*)(b1s + c0);
                float2 wv = *(const float2*)(w2h + c0);
                {
                    float h = ac[0] + bv.x, hw = h * wv.x;
                    ps0 = fmaf(hw, tanhf_approx(0.5f * h), ps0 + hw);
                }
                {
                    float h = ac[1] + bv.y, hw = h * wv.y;
                    ps0 = fmaf(hw, tanhf_approx(0.5f * h), ps0 + hw);
                }
                {
                    float h = ac[2] + bv.x, hw = h * wv.x;
                    ps1 = fmaf(hw, tanhf_approx(0.5f * h), ps1 + hw);
                }
                {
                    float h = ac[3] + bv.y, hw = h * wv.y;
                    ps1 = fmaf(hw, tanhf_approx(0.5f * h), ps1 + hw);
                }
            }
        }
        // reduce across the 4 threads sharing each row (tg = 0..3)
        ps0 += __shfl_xor_sync(0xFFFFFFFFu, ps0, 1);
        ps0 += __shfl_xor_sync(0xFFFFFFFFu, ps0, 2);
        ps1 += __shfl_xor_sync(0xFFFFFFFFu, ps1, 1);
        ps1 += __shfl_xor_sync(0xFFFFFFFFu, ps1, 2);

        if (tg == 0) {
            {
                float e = ps0 + bb + __ldg(aein + rg);
                out[rg] = e;
                int gr;
                if (g_batch_is64) gr = (int)((const long long*)batch)[rg];
                else              gr = ((const int*)batch)[rg];
                atomicAdd(out + NN + gr, e);
            }
            {
                float e = ps1 + bb + __ldg(aein + rg8);
                out[rg8] = e;
                int gr;
                if (g_batch_is64) gr = (int)((const long long*)batch)[rg8];
                else              gr = ((const int*)batch)[rg8];
                atomicAdd(out + NN + gr, e);
            }
        }
        my = nxt;
    }
}

extern "C" void kernel_launch(void* const* d_in, const int* in_sizes, int n_in,
                              void* d_out, int out_size) {
    const float* X     = (const float*)d_in[0];
    const float* aein  = (const float*)d_in[1];
    const void*  batch = d_in[2];
    const float* W1    = (const float*)d_in[3];
    const float* b1    = (const float*)d_in[4];
    const float* W2    = (const float*)d_in[5];
    const float* b2    = (const float*)d_in[6];
    float* out = (float*)d_out;

    init_kernel<<<(NG + 255) / 256, 256>>>(out, (const int*)batch);
    mlp_kernel<<<GRID, TB>>>(X, aein, batch, W1, b1, W2, b2, out);
}

// round 16
// speedup vs baseline: 1.1050x; 1.1050x over previous
#include <cuda_runtime.h>
#include <cuda_bf16.h>
#include <cstdint>

#define NN 500000
#define ND 128
#define NH 64
#define NG 16384
#define TB 256                     // 8 warps per CTA
#define GRID 608                   // 4 CTAs/SM x 152 SMs (full residency set)
#define NTILE (NN / 16)            // 31250 warp-tiles of 16 nodes (exact)
#define NWARPS (GRID * 8)          // 4864 initial tiles via warp id

#define WPITCH 136                 // bf16 per W row (272B = 17*16B: LDSM conflict-free)

__device__ int g_batch_is64;
__device__ unsigned g_ctr;

// Zero graph-energy slots; seed the work-stealing counter; detect batch dtype
// (word NN-1 is the zero int64 high half iff batch stored as int64).
__global__ void init_kernel(float* __restrict__ out, const int* __restrict__ bw) {
    int i = blockIdx.x * blockDim.x + threadIdx.x;
    if (i < NG) out[NN + i] = 0.0f;
    if (i == 0) { g_batch_is64 = (bw[NN - 1] == 0) ? 1 : 0; g_ctr = NWARPS; }
}

__device__ __forceinline__ uint32_t smem_u32(const void* p) {
    uint32_t a;
    asm("{ .reg .u64 t; cvta.to.shared.u64 t, %1; cvt.u32.u64 %0, t; }" : "=r"(a) : "l"(p));
    return a;
}

__device__ __forceinline__ uint32_t pack2(float x, float y) {   // lo half = x
    __nv_bfloat162 h = __floats2bfloat162_rn(x, y);
    return *(uint32_t*)&h;
}

__device__ __forceinline__ void ldsm4(uint32_t* r, uint32_t addr) {
    asm volatile("ldmatrix.sync.aligned.m8n8.x4.shared.b16 {%0,%1,%2,%3}, [%4];"
                 : "=r"(r[0]), "=r"(r[1]), "=r"(r[2]), "=r"(r[3]) : "r"(addr));
}

__device__ __forceinline__ void mma16816(float* d, const uint32_t* a,
                                         uint32_t b0, uint32_t b1) {
    asm volatile(
        "mma.sync.aligned.m16n8k16.row.col.f32.bf16.bf16.f32 "
        "{%0,%1,%2,%3}, {%4,%5,%6,%7}, {%8,%9}, {%0,%1,%2,%3};"
        : "+f"(d[0]), "+f"(d[1]), "+f"(d[2]), "+f"(d[3])
        : "r"(a[0]), "r"(a[1]), "r"(a[2]), "r"(a[3]), "r"(b0), "r"(b1));
}

__device__ __forceinline__ float tanhf_approx(float x) {
    float y;
    asm("tanh.approx.f32 %0, %1;" : "=f"(y) : "f"(x));
    return y;
}

// K-permutation (per 16-col chunk): thread tg supplies logical cols
// {2tg,2tg+1,2tg+8,2tg+9} -> physical {4tg..4tg+3}, so A fragments are one
// float4 per row. W1 staged with the same permutation:
// physical pair p (0..7 in-group) -> logical slot (p&1)*4 + (p>>1).

__global__ __launch_bounds__(TB, 4)
void mlp_kernel(const float* __restrict__ X,
                const float* __restrict__ aein,
                const void*  __restrict__ batch,
                const float* __restrict__ W1,
                const float* __restrict__ b1,
                const float* __restrict__ W2,
                const float* __restrict__ b2,
                float* __restrict__ out)
{
    __shared__ __nv_bfloat16 Ws[NH * WPITCH];   // 17408 B (k-permuted)
    __shared__ float b1s[NH], w2h[NH];          // w2h = W2 * 0.5

    const int tid  = threadIdx.x;
    const int lane = tid & 31;
    const int wid  = tid >> 5;
    const int g  = lane >> 2;
    const int tg = lane & 3;

    // ---- Stage W1 once per CTA (bf16 RN, k-permuted) ----
    #pragma unroll
    for (int q = 0; q < 16; q++) {
        int idx = tid + q * TB;          // 4096 pairs
        int row = idx >> 6;
        int p   = idx & 63;
        int grp = p >> 3;
        int pp  = p & 7;
        int lq  = ((pp & 1) << 2) | (pp >> 1);
        float2 v = *(const float2*)(W1 + (size_t)row * ND + p * 2);
        *(uint32_t*)(Ws + row * WPITCH + grp * 16 + lq * 2) = pack2(v.x, v.y);
    }
    if (tid < NH) { b1s[tid] = b1[tid]; w2h[tid] = 0.5f * W2[tid]; }
    __syncthreads();

    const uint32_t smW = smem_u32(Ws);
    const int bline = (lane & 7) + ((lane >> 4) << 3);
    const int bkoff = (lane & 8) ? 8 : 0;
    const float bb = __ldg(b2);

    // ---- Per-warp work-stealing over 16-node tiles ----
    unsigned my = blockIdx.x * 8 + wid;          // first tile = global warp id
    while (my < NTILE) {
        // steal the next tile early; latency overlaps this tile's work
        unsigned nxt;
        if (lane == 0) nxt = atomicAdd(&g_ctr, 1u);
        nxt = __shfl_sync(0xFFFFFFFFu, nxt, 0);

        // ---- A fragments from global X, phased for MLP=8 ----
        long rg  = (long)my * 16 + g;
        long rg8 = rg + 8;
        const float* pA0 = X + rg  * (long)ND + tg * 4;
        const float* pA1 = X + rg8 * (long)ND + tg * 4;

        uint32_t af[8][4];
        {
            float4 fa[8];                 // 8 LDG.128 in flight (row g)
            #pragma unroll
            for (int k = 0; k < 8; k++) fa[k] = *(const float4*)(pA0 + k * 16);
            #pragma unroll
            for (int k = 0; k < 8; k++) {
                af[k][0] = pack2(fa[k].x, fa[k].y);
                af[k][2] = pack2(fa[k].z, fa[k].w);
            }
            #pragma unroll
            for (int k = 0; k < 8; k++) fa[k] = *(const float4*)(pA1 + k * 16);
            #pragma unroll
            for (int k = 0; k < 8; k++) {
                af[k][1] = pack2(fa[k].x, fa[k].y);
                af[k][3] = pack2(fa[k].z, fa[k].w);
            }
        }

        // ---- GEMM + fused epilogue over 4 col-tile pairs ----
        float ps0 = 0.0f, ps1 = 0.0f;
        #pragma unroll
        for (int jp = 0; jp < 4; jp++) {
            float acc0[4] = {0.f, 0.f, 0.f, 0.f};
            float acc1[4] = {0.f, 0.f, 0.f, 0.f};
            #pragma unroll
            for (int k = 0; k < 8; k++) {
                uint32_t bf[4];
                ldsm4(bf, smW + (uint32_t)(((jp * 16 + bline) * WPITCH + k * 16 + bkoff) * 2));
                mma16816(acc0, af[k], bf[0], bf[1]);
                mma16816(acc1, af[k], bf[2], bf[3]);
            }
            // silu(h)*w2 = (h*w2/2) * (1 + tanh(h/2)); 1 MUFU per h
            #pragma unroll
            for (int t = 0; t < 2; t++) {
                const float* ac = t ? acc1 : acc0;
                int c0 = (jp * 2 + t) * 8 + tg * 2;
                float2 bv = *(const float2*)(b1s + c0);
                float2 wv = *(const float2*)(w2h + c0);
                {
                    float h = ac[0] + bv.x, hw = h * wv.x;
                    ps0 = fmaf(hw, tanhf_approx(0.5f * h), ps0 + hw);
                }
                {
                    float h = ac[1] + bv.y, hw = h * wv.y;
                    ps0 = fmaf(hw, tanhf_approx(0.5f * h), ps0 + hw);
                }
                {
                    float h = ac[2] + bv.x, hw = h * wv.x;
                    ps1 = fmaf(hw, tanhf_approx(0.5f * h), ps1 + hw);
                }
                {
                    float h = ac[3] + bv.y, hw = h * wv.y;
                    ps1 = fmaf(hw, tanhf_approx(0.5f * h), ps1 + hw);
                }
            }
        }
        // reduce across the 4 threads sharing each row (tg = 0..3)
        ps0 += __shfl_xor_sync(0xFFFFFFFFu, ps0, 1);
        ps0 += __shfl_xor_sync(0xFFFFFFFFu, ps0, 2);
        ps1 += __shfl_xor_sync(0xFFFFFFFFu, ps1, 1);
        ps1 += __shfl_xor_sync(0xFFFFFFFFu, ps1, 2);

        if (tg == 0) {
            {
                float e = ps0 + bb + __ldg(aein + rg);
                out[rg] = e;
                int gr;
                if (g_batch_is64) gr = (int)((const long long*)batch)[rg];
                else              gr = ((const int*)batch)[rg];
                atomicAdd(out + NN + gr, e);
            }
            {
                float e = ps1 + bb + __ldg(aein + rg8);
                out[rg8] = e;
                int gr;
                if (g_batch_is64) gr = (int)((const long long*)batch)[rg8];
                else              gr = ((const int*)batch)[rg8];
                atomicAdd(out + NN + gr, e);
            }
        }
        my = nxt;
    }
}

extern "C" void kernel_launch(void* const* d_in, const int* in_sizes, int n_in,
                              void* d_out, int out_size) {
    const float* X     = (const float*)d_in[0];
    const float* aein  = (const float*)d_in[1];
    const void*  batch = d_in[2];
    const float* W1    = (const float*)d_in[3];
    const float* b1    = (const float*)d_in[4];
    const float* W2    = (const float*)d_in[5];
    const float* b2    = (const float*)d_in[6];
    float* out = (float*)d_out;

    init_kernel<<<(NG + 255) / 256, 256>>>(out, (const int*)batch);
    mlp_kernel<<<GRID, TB>>>(X, aein, batch, W1, b1, W2, b2, out);
}

// round 17
// speedup vs baseline: 1.1191x; 1.0127x over previous
#include <cuda_runtime.h>
#include <cuda_bf16.h>
#include <cstdint>

#define NN 500000
#define ND 128
#define NH 64
#define NG 16384
#define TB 512                     // 16 warps per CTA
#define GRID 304                   // 2 CTAs/SM x 152 SMs (32 warps/SM)
#define NTILE (NN / 16)            // 31250 warp-tiles of 16 nodes (exact)
#define NWARPS (GRID * 16)         // 4864 initial tiles via warp id

#define WPITCH 136                 // bf16 per W row (272B = 17*16B: LDSM conflict-free)

__device__ int g_batch_is64;
__device__ unsigned g_ctr;

// Zero graph-energy slots; seed the work-stealing counter; detect batch dtype
// (word NN-1 is the zero int64 high half iff batch stored as int64).
__global__ void init_kernel(float* __restrict__ out, const int* __restrict__ bw) {
    int i = blockIdx.x * blockDim.x + threadIdx.x;
    if (i < NG) out[NN + i] = 0.0f;
    if (i == 0) { g_batch_is64 = (bw[NN - 1] == 0) ? 1 : 0; g_ctr = NWARPS; }
}

__device__ __forceinline__ uint32_t smem_u32(const void* p) {
    uint32_t a;
    asm("{ .reg .u64 t; cvta.to.shared.u64 t, %1; cvt.u32.u64 %0, t; }" : "=r"(a) : "l"(p));
    return a;
}

__device__ __forceinline__ uint32_t pack2(float x, float y) {   // lo half = x
    __nv_bfloat162 h = __floats2bfloat162_rn(x, y);
    return *(uint32_t*)&h;
}

__device__ __forceinline__ void ldsm4(uint32_t* r, uint32_t addr) {
    asm volatile("ldmatrix.sync.aligned.m8n8.x4.shared.b16 {%0,%1,%2,%3}, [%4];"
                 : "=r"(r[0]), "=r"(r[1]), "=r"(r[2]), "=r"(r[3]) : "r"(addr));
}

__device__ __forceinline__ void mma16816(float* d, const uint32_t* a,
                                         uint32_t b0, uint32_t b1) {
    asm volatile(
        "mma.sync.aligned.m16n8k16.row.col.f32.bf16.bf16.f32 "
        "{%0,%1,%2,%3}, {%4,%5,%6,%7}, {%8,%9}, {%0,%1,%2,%3};"
        : "+f"(d[0]), "+f"(d[1]), "+f"(d[2]), "+f"(d[3])
        : "r"(a[0]), "r"(a[1]), "r"(a[2]), "r"(a[3]), "r"(b0), "r"(b1));
}

__device__ __forceinline__ float tanhf_approx(float x) {
    float y;
    asm("tanh.approx.f32 %0, %1;" : "=f"(y) : "f"(x));
    return y;
}

// K-permutation (per 16-col chunk): thread tg supplies logical cols
// {2tg,2tg+1,2tg+8,2tg+9} -> physical {4tg..4tg+3}, so A fragments are one
// float4 per row. W1 staged with the same permutation:
// physical pair p (0..7 in-group) -> logical slot (p&1)*4 + (p>>1).

__global__ __launch_bounds__(TB, 2)
void mlp_kernel(const float* __restrict__ X,
                const float* __restrict__ aein,
                const void*  __restrict__ batch,
                const float* __restrict__ W1,
                const float* __restrict__ b1,
                const float* __restrict__ W2,
                const float* __restrict__ b2,
                float* __restrict__ out)
{
    __shared__ __nv_bfloat16 Ws[NH * WPITCH];   // 17408 B (k-permuted)
    __shared__ float b1s[NH], w2h[NH];          // w2h = W2 * 0.5

    const int tid  = threadIdx.x;
    const int lane = tid & 31;
    const int wid  = tid >> 5;                  // 0..15
    const int g  = lane >> 2;
    const int tg = lane & 3;

    // ---- Stage W1 once per CTA (bf16 RN, k-permuted) ----
    #pragma unroll
    for (int q = 0; q < 8; q++) {
        int idx = tid + q * TB;          // 4096 pairs
        int row = idx >> 6;
        int p   = idx & 63;
        int grp = p >> 3;
        int pp  = p & 7;
        int lq  = ((pp & 1) << 2) | (pp >> 1);
        float2 v = *(const float2*)(W1 + (size_t)row * ND + p * 2);
        *(uint32_t*)(Ws + row * WPITCH + grp * 16 + lq * 2) = pack2(v.x, v.y);
    }
    if (tid < NH) { b1s[tid] = b1[tid]; w2h[tid] = 0.5f * W2[tid]; }
    __syncthreads();

    const uint32_t smW = smem_u32(Ws);
    const int bline = (lane & 7) + ((lane >> 4) << 3);
    const int bkoff = (lane & 8) ? 8 : 0;
    const float bb = __ldg(b2);
    const int is64 = g_batch_is64;               // hoisted once

    // ---- Per-warp work-stealing over 16-node tiles ----
    unsigned my = blockIdx.x * 16 + wid;         // first tile = global warp id
    while (my < NTILE) {
        // steal the next tile early; latency overlaps this tile's work
        unsigned nxt;
        if (lane == 0) nxt = atomicAdd(&g_ctr, 1u);
        nxt = __shfl_sync(0xFFFFFFFFu, nxt, 0);

        unsigned rg  = my * 16 + g;              // 32-bit node indices
        unsigned rg8 = rg + 8;

        // issue aein/batch loads now (tg==0 lanes); hidden under the GEMM
        float ae0 = 0.f, ae1 = 0.f;
        int   gr0 = 0,   gr1 = 0;
        if (tg == 0) {
            ae0 = __ldg(aein + rg);
            ae1 = __ldg(aein + rg8);
            if (is64) {
                gr0 = (int)((const long long*)batch)[rg];
                gr1 = (int)((const long long*)batch)[rg8];
            } else {
                gr0 = ((const int*)batch)[rg];
                gr1 = ((const int*)batch)[rg8];
            }
        }

        // ---- A fragments from global X, phased for MLP=8 ----
        const float* pA0 = X + (size_t)rg  * ND + tg * 4;
        const float* pA1 = X + (size_t)rg8 * ND + tg * 4;

        uint32_t af[8][4];
        {
            float4 fa[8];                 // 8 LDG.128 in flight (row g)
            #pragma unroll
            for (int k = 0; k < 8; k++) fa[k] = *(const float4*)(pA0 + k * 16);
            #pragma unroll
            for (int k = 0; k < 8; k++) {
                af[k][0] = pack2(fa[k].x, fa[k].y);
                af[k][2] = pack2(fa[k].z, fa[k].w);
            }
            #pragma unroll
            for (int k = 0; k < 8; k++) fa[k] = *(const float4*)(pA1 + k * 16);
            #pragma unroll
            for (int k = 0; k < 8; k++) {
                af[k][1] = pack2(fa[k].x, fa[k].y);
                af[k][3] = pack2(fa[k].z, fa[k].w);
            }
        }

        // ---- GEMM + fused epilogue over 4 col-tile pairs ----
        float ps0 = 0.0f, ps1 = 0.0f;
        #pragma unroll
        for (int jp = 0; jp < 4; jp++) {
            float acc0[4] = {0.f, 0.f, 0.f, 0.f};
            float acc1[4] = {0.f, 0.f, 0.f, 0.f};
            #pragma unroll
            for (int k = 0; k < 8; k++) {
                uint32_t bf[4];
                ldsm4(bf, smW + (uint32_t)(((jp * 16 + bline) * WPITCH + k * 16 + bkoff) * 2));
                mma16816(acc0, af[k], bf[0], bf[1]);
                mma16816(acc1, af[k], bf[2], bf[3]);
            }
            // silu(h)*w2 = (h*w2/2) * (1 + tanh(h/2)); 1 MUFU per h
            #pragma unroll
            for (int t = 0; t < 2; t++) {
                const float* ac = t ? acc1 : acc0;
                int c0 = (jp * 2 + t) * 8 + tg * 2;
                float2 bv = *(const float2*)(b1s + c0);
                float2 wv = *(const float2*)(w2h + c0);
                {
                    float h = ac[0] + bv.x, hw = h * wv.x;
                    ps0 = fmaf(hw, tanhf_approx(0.5f * h), ps0 + hw);
                }
                {
                    float h = ac[1] + bv.y, hw = h * wv.y;
                    ps0 = fmaf(hw, tanhf_approx(0.5f * h), ps0 + hw);
                }
                {
                    float h = ac[2] + bv.x, hw = h * wv.x;
                    ps1 = fmaf(hw, tanhf_approx(0.5f * h), ps1 + hw);
                }
                {
                    float h = ac[3] + bv.y, hw = h * wv.y;
                    ps1 = fmaf(hw, tanhf_approx(0.5f * h), ps1 + hw);
                }
            }
        }
        // reduce across the 4 threads sharing each row (tg = 0..3)
        ps0 += __shfl_xor_sync(0xFFFFFFFFu, ps0, 1);
        ps0 += __shfl_xor_sync(0xFFFFFFFFu, ps0, 2);
        ps1 += __shfl_xor_sync(0xFFFFFFFFu, ps1, 1);
        ps1 += __shfl_xor_sync(0xFFFFFFFFu, ps1, 2);

        if (tg == 0) {
            {
                float e = ps0 + bb + ae0;
                out[rg] = e;
                atomicAdd(out + NN + gr0, e);
            }
            {
                float e = ps1 + bb + ae1;
                out[rg8] = e;
                atomicAdd(out + NN + gr1, e);
            }
        }
        my = nxt;
    }
}

extern "C" void kernel_launch(void* const* d_in, const int* in_sizes, int n_in,
                              void* d_out, int out_size) {
    const float* X     = (const float*)d_in[0];
    const float* aein  = (const float*)d_in[1];
    const void*  batch = d_in[2];
    const float* W1    = (const float*)d_in[3];
    const float* b1    = (const float*)d_in[4];
    const float* W2    = (const float*)d_in[5];
    const float* b2    = (const float*)d_in[6];
    float* out = (float*)d_out;

    init_kernel<<<(NG + 255) / 256, 256>>>(out, (const int*)batch);
    mlp_kernel<<<GRID, TB>>>(X, aein, batch, W1, b1, W2, b2, out);
}